// round 5
// baseline (speedup 1.0000x reference)
#include <cuda_runtime.h>
#include <cstdint>
#include <cstddef>

// ---------------------------------------------------------------------------
// SparseDecoder: 4-layer masked MLP, B=64, widths 512->2048->4096->8192->16384
//
// v3: - runtime mask-dtype detection (u8 / i32 / f32 / bf16) -- fixes v2's
//       rel_err 0.255 (mask bytes were being misinterpreted)
//     - CTA-tiled x chunks in shared memory (128 cols x 64 batch = 32 KB) to
//       kill the 2.2 GB L2 x-gather traffic of warp-per-neuron v2
//     - templated rows-per-warp (2/4/8) so every layer fills >=64 CTAs
// ---------------------------------------------------------------------------

#define MAXN 16384
#define BATCH 64

__device__ float g_bufA[MAXN * BATCH];   // activations, [N][64] layout
__device__ float g_bufB[MAXN * BATCH];
__device__ int   g_dtype[4];             // 0=u8, 1=i32, 2=f32, 3=bf16

// ---------------------------------------------------------------------------
// Mask dtype detection. One block per layer; scans first <= 65536 uint32
// words (always within bounds: even u8 gives count bytes = count/4 words).
// Signatures at 5% density are mutually exclusive:
//   bf16 true in lo-half -> (w & 0xFFFF) == 0x3F80   (never occurs for others)
//   f32  true            -> w == 0x3F800000          (u8/i32 can't produce)
//   u8 multi-byte        -> bytes all in {0,1}, w > 1 (i32 words are only 0/1)
//   i32                  -> only w == 1 ever seen
// ---------------------------------------------------------------------------
__global__ void detect_dtype_kernel(const void* m0, long n0, const void* m1, long n1,
                                    const void* m2, long n2, const void* m3, long n3) {
    const void* ms[4] = {m0, m1, m2, m3};
    long        ns[4] = {n0, n1, n2, n3};
    int L = blockIdx.x;
    const unsigned int* p = (const unsigned int*)ms[L];
    long nw = ns[L] >> 2;
    if (nw > 65536) nw = 65536;

    unsigned int f = 0;
    for (long i = threadIdx.x; i < nw; i += blockDim.x) {
        unsigned int w = __ldg(p + i);
        if (w == 0u) continue;
        if ((w & 0xFFFFu) == 0x3F80u) f |= 1u;                // bf16
        if (w == 0x3F800000u)         f |= 2u;                // f32
        if ((w & 0xFEFEFEFEu) == 0u && w > 1u) f |= 4u;       // u8
        if (w == 1u)                  f |= 8u;                // i32 (or u8 byte0)
    }
    __shared__ unsigned int sf;
    if (threadIdx.x == 0) sf = 0;
    __syncthreads();
    atomicOr(&sf, f);
    __syncthreads();
    if (threadIdx.x == 0) {
        unsigned int ff = sf;
        int dt;
        if      (ff & 1u) dt = 3;
        else if (ff & 2u) dt = 2;
        else if (ff & 4u) dt = 0;
        else if (ff & 8u) dt = 1;
        else              dt = 0;
        g_dtype[L] = dt;
    }
}

// ---------------------------------------------------------------------------
// Tiled transpose: dst[C][R] = src[R][C].  grid (ceil(C/32), ceil(R/32)), block (32,8)
// ---------------------------------------------------------------------------
__global__ void transpose_kernel(const float* __restrict__ src,
                                 float* __restrict__ dst, int R, int C) {
    __shared__ float tile[32][33];
    int c0 = blockIdx.x * 32;
    int r0 = blockIdx.y * 32;
    int tx = threadIdx.x, ty = threadIdx.y;
    #pragma unroll
    for (int i = ty; i < 32; i += 8) {
        int r = r0 + i, c = c0 + tx;
        if (r < R && c < C) tile[i][tx] = src[(size_t)r * C + c];
    }
    __syncthreads();
    #pragma unroll
    for (int i = ty; i < 32; i += 8) {
        int c = c0 + i, r = r0 + tx;
        if (c < C && r < R) dst[(size_t)c * R + r] = tile[tx][i];
    }
}

// ---------------------------------------------------------------------------
// Sparse layer: out[N_out][64] = act( (W*mask) @ x + b ), x given as [N_in][64].
//
// 512 threads = 16 warps per CTA; each warp owns RPW output rows (acc in regs,
// lane l holds batch elements 2l, 2l+1). x is staged in 128-column chunks in
// shared memory. Mask scanned 4 columns/lane -> nibble -> 4 ballots; each
// nonzero costs: 1 broadcast LDG (W), 1 conflict-free LDS.64 (x), 2 FMA/lane.
// ---------------------------------------------------------------------------
template <int RPW>
__global__ __launch_bounds__(512)
void sparse_layer_kernel(const float* __restrict__ W,
                         const float* __restrict__ bias,
                         const void*  __restrict__ mask,
                         const float* __restrict__ xin,   // [N_in][64]
                         float*       __restrict__ out,   // [N_out][64]
                         int N_in, int layer, int relu) {
    __shared__ float sx[128 * 64];   // 32 KB chunk of x

    const int tid  = threadIdx.x;
    const int lane = tid & 31;
    const int wid  = tid >> 5;                      // 0..15
    const int row0 = blockIdx.x * (RPW * 16) + wid * RPW;
    const int dt   = g_dtype[layer];

    float acc[RPW][2];
    #pragma unroll
    for (int r = 0; r < RPW; r++) acc[r][0] = acc[r][1] = 0.f;

    for (int c0 = 0; c0 < N_in; c0 += 128) {
        __syncthreads();   // prior chunk fully consumed
        {
            const float4* src  = (const float4*)(xin + (size_t)c0 * BATCH);
            float4*       dst4 = (float4*)sx;
            #pragma unroll
            for (int i = 0; i < 4; i++)            // 2048 float4 / 512 threads
                dst4[tid + i * 512] = __ldg(src + tid + i * 512);
        }
        __syncthreads();

        #pragma unroll
        for (int r = 0; r < RPW; r++) {
            const int   row  = row0 + r;
            const float* wrow = W + (size_t)row * N_in;
            const size_t eidx = (size_t)row * N_in + c0 + (lane << 2); // 4 cols/lane

            unsigned int nib;
            if (dt == 0) {               // u8
                unsigned int v = __ldg((const unsigned int*)((const unsigned char*)mask + eidx));
                unsigned int c = __vcmpne4(v, 0u);
                nib = (c & 1u) | ((c >> 7) & 2u) | ((c >> 14) & 4u) | ((c >> 21) & 8u);
            } else if (dt == 3) {        // bf16
                uint2 v = __ldg((const uint2*)((const unsigned short*)mask + eidx));
                nib = (unsigned)((v.x & 0xFFFFu) != 0u)
                    | ((unsigned)((v.x >> 16)     != 0u) << 1)
                    | ((unsigned)((v.y & 0xFFFFu) != 0u) << 2)
                    | ((unsigned)((v.y >> 16)     != 0u) << 3);
            } else {                     // i32 / f32 (nonzero word == true)
                uint4 v = __ldg((const uint4*)((const unsigned int*)mask + eidx));
                nib = (unsigned)(v.x != 0u)
                    | ((unsigned)(v.y != 0u) << 1)
                    | ((unsigned)(v.z != 0u) << 2)
                    | ((unsigned)(v.w != 0u) << 3);
            }

            #pragma unroll
            for (int sub = 0; sub < 4; ++sub) {
                unsigned int bm = __ballot_sync(0xffffffffu, (nib >> sub) & 1u);
                while (bm) {
                    int l = __ffs(bm) - 1;
                    bm &= bm - 1;
                    int j  = c0 + (l << 2) + sub;        // global column
                    float wv = __ldg(wrow + j);          // broadcast, 1 sector
                    float2 xv = *(const float2*)(sx + (((l << 2) + sub) << 6) + (lane << 1));
                    acc[r][0] = fmaf(wv, xv.x, acc[r][0]);
                    acc[r][1] = fmaf(wv, xv.y, acc[r][1]);
                }
            }
        }
    }

    #pragma unroll
    for (int r = 0; r < RPW; r++) {
        int row = row0 + r;
        float bb = __ldg(bias + row);
        float a0 = acc[r][0] + bb;
        float a1 = acc[r][1] + bb;
        if (relu) { a0 = fmaxf(a0, 0.f); a1 = fmaxf(a1, 0.f); }
        float2 v; v.x = a0; v.y = a1;
        *(float2*)(out + ((size_t)row << 6) + (lane << 1)) = v;
    }
}

// ---------------------------------------------------------------------------
// Host launcher
// ---------------------------------------------------------------------------
extern "C" void kernel_launch(void* const* d_in, const int* in_sizes, int n_in,
                              void* d_out, int out_size) {
    static const int S[5] = {512, 2048, 4096, 8192, 16384};

    // Identify inputs by element count. x: 64*512 unique. b_i: S[i+1] unique.
    // W_i and mask_i share a count; W precedes mask in signature, dict and
    // alphabetical orderings alike.
    const float* x = nullptr;
    const float* W[4] = {};
    const float* b[4] = {};
    const void*  m[4] = {};

    for (int i = 0; i < n_in; i++) {
        long sz = (long)in_sizes[i];
        if (sz == 64L * 512L) { if (!x) x = (const float*)d_in[i]; continue; }
        for (int L = 0; L < 4; L++) {
            long wsz = (long)S[L + 1] * (long)S[L];
            if (sz == wsz) {
                if (!W[L]) W[L] = (const float*)d_in[i];
                else if (!m[L]) m[L] = d_in[i];
                break;
            }
            if (sz == (long)S[L + 1]) { b[L] = (const float*)d_in[i]; break; }
        }
    }

    float* bufA = nullptr;
    float* bufB = nullptr;
    cudaGetSymbolAddress((void**)&bufA, g_bufA);
    cudaGetSymbolAddress((void**)&bufB, g_bufB);

    // 1) classify mask dtypes (device-side, graph-capturable)
    detect_dtype_kernel<<<4, 256>>>(m[0], (long)S[1] * S[0],
                                    m[1], (long)S[2] * S[1],
                                    m[2], (long)S[3] * S[2],
                                    m[3], (long)S[4] * S[3]);

    // 2) x [64][512] -> bufA [512][64]
    {
        dim3 tb(32, 8);
        transpose_kernel<<<dim3(16, 2), tb>>>(x, bufA, 64, 512);
    }

    // 3) four sparse layers, ping-pong A->B->A->B->A
    sparse_layer_kernel<2><<<S[1] / 32,  512>>>(W[0], b[0], m[0], bufA, bufB, S[0], 0, 1);
    sparse_layer_kernel<2><<<S[2] / 32,  512>>>(W[1], b[1], m[1], bufB, bufA, S[1], 1, 1);
    sparse_layer_kernel<4><<<S[3] / 64,  512>>>(W[2], b[2], m[2], bufA, bufB, S[2], 2, 1);
    sparse_layer_kernel<8><<<S[4] / 128, 512>>>(W[3], b[3], m[3], bufB, bufA, S[3], 3, 0);

    // 4) bufA [16384][64] -> d_out [64][16384]
    {
        dim3 tb(32, 8);
        transpose_kernel<<<dim3(2, 512), tb>>>(bufA, (float*)d_out, 16384, 64);
    }
    (void)out_size;
}

// round 6
// speedup vs baseline: 5.2372x; 5.2372x over previous
#include <cuda_runtime.h>
#include <cstdint>
#include <cstddef>

// ---------------------------------------------------------------------------
// SparseDecoder: 4-layer masked MLP, B=64, widths 512->2048->4096->8192->16384
//
// v4: - lane-owned predicated LDG.128 of W + shfl-based gather (kills the
//       per-nz broadcast-LDG latency chain that made v3 2811 us)
//     - two-phase chunk body: all mask+W loads issued, then ballot extraction
//     - grids >= 128-256 CTAs for every layer (RPW 1/1/2/4)
// ---------------------------------------------------------------------------

#define MAXN 16384
#define BATCH 64

__device__ float g_bufA[MAXN * BATCH];   // activations, [N][64] layout
__device__ float g_bufB[MAXN * BATCH];
__device__ int   g_dtype[4];             // 0=u8, 1=i32, 2=f32, 3=bf16

// ---------------------------------------------------------------------------
// Mask dtype detection (unchanged from v3 — it works).
// ---------------------------------------------------------------------------
__global__ void detect_dtype_kernel(const void* m0, long n0, const void* m1, long n1,
                                    const void* m2, long n2, const void* m3, long n3) {
    const void* ms[4] = {m0, m1, m2, m3};
    long        ns[4] = {n0, n1, n2, n3};
    int L = blockIdx.x;
    const unsigned int* p = (const unsigned int*)ms[L];
    long nw = ns[L] >> 2;
    if (nw > 65536) nw = 65536;

    unsigned int f = 0;
    for (long i = threadIdx.x; i < nw; i += blockDim.x) {
        unsigned int w = __ldg(p + i);
        if (w == 0u) continue;
        if ((w & 0xFFFFu) == 0x3F80u) f |= 1u;                // bf16
        if (w == 0x3F800000u)         f |= 2u;                // f32
        if ((w & 0xFEFEFEFEu) == 0u && w > 1u) f |= 4u;       // u8
        if (w == 1u)                  f |= 8u;                // i32 (or u8 byte0)
    }
    __shared__ unsigned int sf;
    if (threadIdx.x == 0) sf = 0;
    __syncthreads();
    atomicOr(&sf, f);
    __syncthreads();
    if (threadIdx.x == 0) {
        unsigned int ff = sf;
        int dt;
        if      (ff & 1u) dt = 3;
        else if (ff & 2u) dt = 2;
        else if (ff & 4u) dt = 0;
        else if (ff & 8u) dt = 1;
        else              dt = 0;
        g_dtype[L] = dt;
    }
}

// ---------------------------------------------------------------------------
// Tiled transpose: dst[C][R] = src[R][C].  grid (ceil(C/32), ceil(R/32)), block (32,8)
// ---------------------------------------------------------------------------
__global__ void transpose_kernel(const float* __restrict__ src,
                                 float* __restrict__ dst, int R, int C) {
    __shared__ float tile[32][33];
    int c0 = blockIdx.x * 32;
    int r0 = blockIdx.y * 32;
    int tx = threadIdx.x, ty = threadIdx.y;
    #pragma unroll
    for (int i = ty; i < 32; i += 8) {
        int r = r0 + i, c = c0 + tx;
        if (r < R && c < C) tile[i][tx] = src[(size_t)r * C + c];
    }
    __syncthreads();
    #pragma unroll
    for (int i = ty; i < 32; i += 8) {
        int c = c0 + i, r = r0 + tx;
        if (c < C && r < R) dst[(size_t)c * R + r] = tile[tx][i];
    }
}

// ---------------------------------------------------------------------------
// mask-word -> 4-bit nonzero nibble for lane's 4 columns, per dtype
// ---------------------------------------------------------------------------
__device__ __forceinline__ unsigned int load_nib(const void* mask, size_t eidx, int dt) {
    if (dt == 0) {               // u8
        unsigned int v = __ldg((const unsigned int*)((const unsigned char*)mask + eidx));
        unsigned int c = __vcmpne4(v, 0u);
        return (c & 1u) | ((c >> 7) & 2u) | ((c >> 14) & 4u) | ((c >> 21) & 8u);
    } else if (dt == 3) {        // bf16
        uint2 v = __ldg((const uint2*)((const unsigned short*)mask + eidx));
        return (unsigned)((v.x & 0xFFFFu) != 0u)
             | ((unsigned)((v.x >> 16)     != 0u) << 1)
             | ((unsigned)((v.y & 0xFFFFu) != 0u) << 2)
             | ((unsigned)((v.y >> 16)     != 0u) << 3);
    } else {                     // i32 / f32 (nonzero word == true)
        uint4 v = __ldg((const uint4*)((const unsigned int*)mask + eidx));
        return (unsigned)(v.x != 0u)
             | ((unsigned)(v.y != 0u) << 1)
             | ((unsigned)(v.z != 0u) << 2)
             | ((unsigned)(v.w != 0u) << 3);
    }
}

// ---------------------------------------------------------------------------
// Sparse layer: out[N_out][64] = act( (W*mask) @ x + b ), x as [N_in][64].
// 512 threads = 16 warps; warp owns RPW rows; lane owns batch elems 2l,2l+1.
// Per 128-col chunk per row:
//   phase 1: mask word (4 cols/lane) + predicated dense LDG.128 of own W cols
//   phase 2: 4 ballots; per nz: shfl W from owning lane + LDS.64 x + 2 FMA
// ---------------------------------------------------------------------------
template <int RPW>
__global__ __launch_bounds__(512)
void sparse_layer_kernel(const float* __restrict__ W,
                         const float* __restrict__ bias,
                         const void*  __restrict__ mask,
                         const float* __restrict__ xin,   // [N_in][64]
                         float*       __restrict__ out,   // [N_out][64]
                         int N_in, int layer, int relu) {
    __shared__ float sx[128 * 64];   // 32 KB chunk of x

    const int tid  = threadIdx.x;
    const int lane = tid & 31;
    const int wid  = tid >> 5;                      // 0..15
    const int row0 = blockIdx.x * (RPW * 16) + wid * RPW;
    const int dt   = g_dtype[layer];

    float accx[RPW], accy[RPW];
    #pragma unroll
    for (int r = 0; r < RPW; r++) { accx[r] = 0.f; accy[r] = 0.f; }

    for (int c0 = 0; c0 < N_in; c0 += 128) {
        __syncthreads();   // previous chunk fully consumed
        {
            const float4* src  = (const float4*)(xin + (size_t)c0 * BATCH);
            float4*       dst4 = (float4*)sx;
            #pragma unroll
            for (int i = 0; i < 4; i++)            // 2048 float4 / 512 threads
                dst4[tid + i * 512] = __ldg(src + tid + i * 512);
        }
        __syncthreads();

        // ---- phase 1: issue all mask + W loads for this chunk (MLP = 2*RPW)
        unsigned int nib[RPW];
        float4       wv[RPW];
        #pragma unroll
        for (int r = 0; r < RPW; r++) {
            const size_t base = (size_t)(row0 + r) * N_in + c0 + (lane << 2);
            nib[r] = load_nib(mask, base, dt);
            if (nib[r]) wv[r] = __ldg((const float4*)(W + base));
        }

        // ---- phase 2: ballot extraction; W via shfl, x via conflict-free LDS
        #pragma unroll
        for (int r = 0; r < RPW; r++) {
            #pragma unroll
            for (int sub = 0; sub < 4; ++sub) {
                unsigned int bm = __ballot_sync(0xffffffffu, (nib[r] >> sub) & 1u);
                const float wsub = (sub == 0) ? wv[r].x
                                 : (sub == 1) ? wv[r].y
                                 : (sub == 2) ? wv[r].z : wv[r].w;
                while (bm) {
                    int l = __ffs(bm) - 1;
                    bm &= bm - 1;
                    float wj = __shfl_sync(0xffffffffu, wsub, l);
                    float2 xv = *(const float2*)(sx + (((l << 2) + sub) << 6) + (lane << 1));
                    accx[r] = fmaf(wj, xv.x, accx[r]);
                    accy[r] = fmaf(wj, xv.y, accy[r]);
                }
            }
        }
    }

    #pragma unroll
    for (int r = 0; r < RPW; r++) {
        int row = row0 + r;
        float bb = __ldg(bias + row);
        float a0 = accx[r] + bb;
        float a1 = accy[r] + bb;
        if (relu) { a0 = fmaxf(a0, 0.f); a1 = fmaxf(a1, 0.f); }
        float2 v; v.x = a0; v.y = a1;
        *(float2*)(out + ((size_t)row << 6) + (lane << 1)) = v;
    }
}

// ---------------------------------------------------------------------------
// Host launcher
// ---------------------------------------------------------------------------
extern "C" void kernel_launch(void* const* d_in, const int* in_sizes, int n_in,
                              void* d_out, int out_size) {
    static const int S[5] = {512, 2048, 4096, 8192, 16384};

    const float* x = nullptr;
    const float* W[4] = {};
    const float* b[4] = {};
    const void*  m[4] = {};

    for (int i = 0; i < n_in; i++) {
        long sz = (long)in_sizes[i];
        if (sz == 64L * 512L) { if (!x) x = (const float*)d_in[i]; continue; }
        for (int L = 0; L < 4; L++) {
            long wsz = (long)S[L + 1] * (long)S[L];
            if (sz == wsz) {
                if (!W[L]) W[L] = (const float*)d_in[i];
                else if (!m[L]) m[L] = d_in[i];
                break;
            }
            if (sz == (long)S[L + 1]) { b[L] = (const float*)d_in[i]; break; }
        }
    }

    float* bufA = nullptr;
    float* bufB = nullptr;
    cudaGetSymbolAddress((void**)&bufA, g_bufA);
    cudaGetSymbolAddress((void**)&bufB, g_bufB);

    // 1) classify mask dtypes
    detect_dtype_kernel<<<4, 256>>>(m[0], (long)S[1] * S[0],
                                    m[1], (long)S[2] * S[1],
                                    m[2], (long)S[3] * S[2],
                                    m[3], (long)S[4] * S[3]);

    // 2) x [64][512] -> bufA [512][64]
    {
        dim3 tb(32, 8);
        transpose_kernel<<<dim3(16, 2), tb>>>(x, bufA, 64, 512);
    }

    // 3) four sparse layers, ping-pong A->B->A->B->A
    //    grids: 128 / 256 / 256 / 256 CTAs of 16 warps
    sparse_layer_kernel<1><<<S[1] / 16, 512>>>(W[0], b[0], m[0], bufA, bufB, S[0], 0, 1);
    sparse_layer_kernel<1><<<S[2] / 16, 512>>>(W[1], b[1], m[1], bufB, bufA, S[1], 1, 1);
    sparse_layer_kernel<2><<<S[3] / 32, 512>>>(W[2], b[2], m[2], bufA, bufB, S[2], 2, 1);
    sparse_layer_kernel<4><<<S[4] / 64, 512>>>(W[3], b[3], m[3], bufB, bufA, S[3], 3, 0);

    // 4) bufA [16384][64] -> d_out [64][16384]
    {
        dim3 tb(32, 8);
        transpose_kernel<<<dim3(2, 512), tb>>>(bufA, (float*)d_out, 16384, 64);
    }
    (void)out_size;
}